// round 13
// baseline (speedup 1.0000x reference)
#include <cuda_runtime.h>
#include <cuda_bf16.h>
#include <cuda_fp16.h>
#include <cstdint>

#define NN 50000
#define NE 800000
#define LN_EPS 1e-5f
#define NEG_SLOPE 0.2f
#define NPART 49
#define HALF1 25088   // 196*128 ; first row/node partition

// ---------------- static scratch (no allocs allowed) ----------------
__device__ __half2 g_hw[(size_t)NN * 128];          // GEMM output h, fp16
__device__ __nv_bfloat16 g_ah[(size_t)NN * 256];    // A hi (x split, then feat hi)
__device__ __nv_bfloat16 g_al[(size_t)NN * 256];    // A lo
__device__ __nv_bfloat16 g_wth1[256 * 256];
__device__ __nv_bfloat16 g_wtl1[256 * 256];
__device__ __nv_bfloat16 g_wth2[256 * 256];
__device__ __nv_bfloat16 g_wtl2[256 * 256];
__device__ __nv_bfloat16 g_wth3[256 * 64];
__device__ __nv_bfloat16 g_wtl3[256 * 64];
__device__ float g_als[(size_t)NN * 4];
__device__ float g_ald[(size_t)NN * 4];
__device__ int   g_count[NN];
__device__ int   g_rowstart[NN];
__device__ int   g_cursor[NN];
__device__ int   g_csr[NE];
__device__ int   g_part[NPART];
__device__ int   g_partscan[NPART];
__device__ int   g_is64;

// ---------------- helpers ----------------
__device__ __forceinline__ uint32_t smem_u32(const void* p) {
    uint32_t a;
    asm("{ .reg .u64 t; cvta.to.shared.u64 t, %1; cvt.u32.u64 %0, t; }" : "=r"(a) : "l"(p));
    return a;
}
__device__ __forceinline__ void ldmx4(uint32_t* r, uint32_t addr) {
    asm volatile("ldmatrix.sync.aligned.m8n8.x4.shared.b16 {%0,%1,%2,%3}, [%4];"
                 : "=r"(r[0]), "=r"(r[1]), "=r"(r[2]), "=r"(r[3]) : "r"(addr));
}
__device__ __forceinline__ void mma16816(float* c, const uint32_t* a, uint32_t b0, uint32_t b1) {
    asm volatile("mma.sync.aligned.m16n8k16.row.col.f32.bf16.bf16.f32 "
                 "{%0,%1,%2,%3}, {%4,%5,%6,%7}, {%8,%9}, {%0,%1,%2,%3};"
                 : "+f"(c[0]), "+f"(c[1]), "+f"(c[2]), "+f"(c[3])
                 : "r"(a[0]), "r"(a[1]), "r"(a[2]), "r"(a[3]), "r"(b0), "r"(b1));
}
__device__ __forceinline__ void cpa16(uint32_t d, const void* s) {
    asm volatile("cp.async.ca.shared.global [%0], [%1], 16;" :: "r"(d), "l"(s));
}
#define CP_COMMIT() asm volatile("cp.async.commit_group;" ::: "memory")
#define CP_WAIT(n)  asm volatile("cp.async.wait_group %0;" :: "n"(n) : "memory")

__device__ __forceinline__ float lrelu(float v) { return v >= 0.0f ? v : NEG_SLOPE * v; }
__device__ __forceinline__ int load_idx(const void* ei, long long pos) {
    if (g_is64) return (int)((const long long*)ei)[pos];
    return ((const int*)ei)[pos];
}

// ---------------- edge-index width detection ----------------
__global__ void detect_width(const void* ei) {
    const int* p = (const int*)ei;
    int is64 = 1;
    for (int i = 0; i < 16; i++)
        if (p[2 * i + 1] != 0) { is64 = 0; break; }
    g_is64 = is64;
}

// ---------------- CSR build ----------------
__global__ void zero_counts() {
    int i = blockIdx.x * blockDim.x + threadIdx.x;
    if (i < NN) g_count[i] = 0;
}
__global__ void count_edges(const void* __restrict__ ei) {
    int i = blockIdx.x * blockDim.x + threadIdx.x;
    if (i >= NE) return;
    atomicAdd(&g_count[load_idx(ei, (long long)NE + i)], 1);
}
__global__ void scan_stage1() {
    int b = blockIdx.x, t = threadIdx.x;
    int base = b * 1024 + t * 4;
    int s = 0;
#pragma unroll
    for (int j = 0; j < 4; j++) { int idx = base + j; if (idx < NN) s += g_count[idx]; }
    __shared__ int sm[256];
    sm[t] = s;
    __syncthreads();
    for (int off = 128; off > 0; off >>= 1) { if (t < off) sm[t] += sm[t + off]; __syncthreads(); }
    if (t == 0) g_part[b] = sm[0];
}
__global__ void scan_stage2() {
    if (threadIdx.x == 0) {
        int run = 0;
        for (int i = 0; i < NPART; i++) { g_partscan[i] = run; run += g_part[i]; }
    }
}
__global__ void scan_stage3() {
    int b = blockIdx.x, t = threadIdx.x;
    int base = b * 1024 + t * 4;
    int v[4]; int tsum = 0;
#pragma unroll
    for (int j = 0; j < 4; j++) { int idx = base + j; v[j] = (idx < NN) ? g_count[idx] : 0; tsum += v[j]; }
    __shared__ int sm[256];
    sm[t] = tsum;
    __syncthreads();
    for (int off = 1; off < 256; off <<= 1) {
        int add = (t >= off) ? sm[t - off] : 0;
        __syncthreads(); sm[t] += add; __syncthreads();
    }
    int run = g_partscan[b] + sm[t] - tsum;
#pragma unroll
    for (int j = 0; j < 4; j++) {
        int idx = base + j;
        if (idx < NN) { g_rowstart[idx] = run; g_cursor[idx] = run; run += v[j]; }
    }
}
__global__ void scatter_edges(const void* __restrict__ ei) {
    int i = blockIdx.x * blockDim.x + threadIdx.x;
    if (i >= NE) return;
    int src = load_idx(ei, i);
    int dst = load_idx(ei, (long long)NE + i);
    g_csr[atomicAdd(&g_cursor[dst], 1)] = src;
}

// ---------------- operand pre-splitting ----------------
__global__ void split_input(const float* __restrict__ x, __nv_bfloat16* __restrict__ xh,
                            __nv_bfloat16* __restrict__ xl, int n2) {
    int i = blockIdx.x * 256 + threadIdx.x;
    if (i >= n2) return;
    float2 v = ((const float2*)x)[i];
    __nv_bfloat16 hx = __float2bfloat16(v.x), hy = __float2bfloat16(v.y);
    ((__nv_bfloat162*)xh)[i] = __nv_bfloat162(hx, hy);
    ((__nv_bfloat162*)xl)[i] = __nv_bfloat162(__float2bfloat16(v.x - __bfloat162float(hx)),
                                              __float2bfloat16(v.y - __bfloat162float(hy)));
}
__global__ void transposeW_split(const float* __restrict__ W, __nv_bfloat16* __restrict__ Wth,
                                 __nv_bfloat16* __restrict__ Wtl, int K, int Ncol) {
    int i = blockIdx.x * 256 + threadIdx.x;
    if (i < K * Ncol) {
        int k = i / Ncol, n = i % Ncol;
        float v = W[i];
        __nv_bfloat16 h = __float2bfloat16(v);
        Wth[n * K + k] = h;
        Wtl[n * K + k] = __float2bfloat16(v - __bfloat162float(h));
    }
}

// ---------------- pipelined bf16x3 GEMM (pre-split operands, row-offset) ----------------
#define LDA 40
#define ABUF 10240
#define BBUF 5120
#define OFF_AH 0
#define OFF_AL 20480
#define OFF_BH 40960
#define OFF_BL 51200
#define OFF_PS 61440
#define OFF_PD 62464
#define GEMM_SMEM 63488

__global__ void __launch_bounds__(256) gemm_bf16p(const __nv_bfloat16* __restrict__ Ah,
                                                  const __nv_bfloat16* __restrict__ Al,
                                                  const __nv_bfloat16* __restrict__ Bh,
                                                  const __nv_bfloat16* __restrict__ Bl,
                                                  __half2* __restrict__ C,
                                                  const float* __restrict__ a_s,
                                                  const float* __restrict__ a_d,
                                                  float* __restrict__ als,
                                                  float* __restrict__ ald,
                                                  int rowOff, int M, int K, int Ncol, int H) {
    extern __shared__ char smem[];
    uint32_t sb = smem_u32(smem);
    float* sPs = (float*)(smem + OFF_PS);
    float* sPd = (float*)(smem + OFF_PD);

    int tid = threadIdx.x;
    int lane = tid & 31, wid = tid >> 5;
    int warpM = wid & 3, warpN = wid >> 2;
    int rowBase = rowOff + blockIdx.x * 128, colBase = blockIdx.y * 64;
    int head = blockIdx.y;

    float acc[2][4][4];
#pragma unroll
    for (int i = 0; i < 2; i++)
#pragma unroll
        for (int j = 0; j < 4; j++)
#pragma unroll
            for (int q = 0; q < 4; q++) acc[i][j][q] = 0.0f;

    int ar0 = tid >> 2, ac0 = (tid & 3) * 8;
    int ar1 = (tid + 256) >> 2;
    int rg0 = rowBase + ar0; if (rg0 >= M) rg0 = M - 1;
    int rg1 = rowBase + ar1; if (rg1 >= M) rg1 = M - 1;
    int br = tid >> 2, bc = (tid & 3) * 8;
    int brg = colBase + br;

    auto load_tile = [&](int t, int b) {
        int kt = t * 32;
        uint32_t aH = sb + OFF_AH + b * ABUF;
        uint32_t aL = sb + OFF_AL + b * ABUF;
        uint32_t bH = sb + OFF_BH + b * BBUF;
        uint32_t bL = sb + OFF_BL + b * BBUF;
        cpa16(aH + (ar0 * LDA + ac0) * 2, Ah + (size_t)rg0 * K + kt + ac0);
        cpa16(aH + (ar1 * LDA + ac0) * 2, Ah + (size_t)rg1 * K + kt + ac0);
        cpa16(aL + (ar0 * LDA + ac0) * 2, Al + (size_t)rg0 * K + kt + ac0);
        cpa16(aL + (ar1 * LDA + ac0) * 2, Al + (size_t)rg1 * K + kt + ac0);
        cpa16(bH + (br * LDA + bc) * 2, Bh + (size_t)brg * K + kt + bc);
        cpa16(bL + (br * LDA + bc) * 2, Bl + (size_t)brg * K + kt + bc);
    };

    int rowA = warpM * 32 + (lane & 15);
    int colA = (lane >> 4) * 8;
    int rowB = warpN * 32 + (lane & 7) + ((lane >> 4) << 3);
    int colB = ((lane >> 3) & 1) * 8;

    int nT = K >> 5;
    load_tile(0, 0);
    CP_COMMIT();

    int buf = 0;
    for (int t = 0; t < nT; t++) {
        if (t + 1 < nT) {
            load_tile(t + 1, buf ^ 1);
            CP_COMMIT();
            CP_WAIT(1);
        } else {
            CP_WAIT(0);
        }
        __syncthreads();

        uint32_t aHiB = sb + OFF_AH + buf * ABUF;
        uint32_t aLoB = sb + OFF_AL + buf * ABUF;
        uint32_t bHiB = sb + OFF_BH + buf * BBUF;
        uint32_t bLoB = sb + OFF_BL + buf * BBUF;
#pragma unroll
        for (int ks = 0; ks < 2; ks++) {
            int k0 = ks * 16;
            uint32_t ah[2][4], al[2][4];
#pragma unroll
            for (int tm = 0; tm < 2; tm++) {
                uint32_t off = (uint32_t)(((rowA + tm * 16) * LDA + k0 + colA) * 2);
                ldmx4(ah[tm], aHiB + off);
                ldmx4(al[tm], aLoB + off);
            }
            uint32_t bh[2][4], bl[2][4];
#pragma unroll
            for (int g = 0; g < 2; g++) {
                uint32_t off = (uint32_t)(((rowB + g * 16) * LDA + k0 + colB) * 2);
                ldmx4(bh[g], bHiB + off);
                ldmx4(bl[g], bLoB + off);
            }
#pragma unroll
            for (int tm = 0; tm < 2; tm++) {
#pragma unroll
                for (int tn = 0; tn < 4; tn++) {
                    int g = tn >> 1, q = (tn & 1) * 2;
                    mma16816(acc[tm][tn], ah[tm], bh[g][q], bh[g][q + 1]);
                    mma16816(acc[tm][tn], ah[tm], bl[g][q], bl[g][q + 1]);
                    mma16816(acc[tm][tn], al[tm], bh[g][q], bh[g][q + 1]);
                }
            }
        }
        __syncthreads();
        buf ^= 1;
    }

#pragma unroll
    for (int tm = 0; tm < 2; tm++) {
        int r0 = rowBase + warpM * 32 + tm * 16 + (lane >> 2);
#pragma unroll
        for (int tn = 0; tn < 4; tn++) {
            int c = colBase + warpN * 32 + tn * 8 + (lane & 3) * 2;
            if (r0 < M)
                C[((size_t)r0 * Ncol + c) >> 1] = __floats2half2_rn(acc[tm][tn][0], acc[tm][tn][1]);
            if (r0 + 8 < M)
                C[((size_t)(r0 + 8) * Ncol + c) >> 1] = __floats2half2_rn(acc[tm][tn][2], acc[tm][tn][3]);
        }
    }

    float asv[8], adv[8];
#pragma unroll
    for (int tn = 0; tn < 4; tn++) {
        int cl = warpN * 32 + tn * 8 + (lane & 3) * 2;
        asv[tn * 2] = a_s[head * 64 + cl];
        asv[tn * 2 + 1] = a_s[head * 64 + cl + 1];
        adv[tn * 2] = a_d[head * 64 + cl];
        adv[tn * 2 + 1] = a_d[head * 64 + cl + 1];
    }
#pragma unroll
    for (int tm = 0; tm < 2; tm++) {
#pragma unroll
        for (int half = 0; half < 2; half++) {
            float ps = 0.0f, pd = 0.0f;
#pragma unroll
            for (int tn = 0; tn < 4; tn++) {
                ps += acc[tm][tn][half * 2] * asv[tn * 2] + acc[tm][tn][half * 2 + 1] * asv[tn * 2 + 1];
                pd += acc[tm][tn][half * 2] * adv[tn * 2] + acc[tm][tn][half * 2 + 1] * adv[tn * 2 + 1];
            }
            ps += __shfl_xor_sync(0xffffffffu, ps, 1);
            ps += __shfl_xor_sync(0xffffffffu, ps, 2);
            pd += __shfl_xor_sync(0xffffffffu, pd, 1);
            pd += __shfl_xor_sync(0xffffffffu, pd, 2);
            if ((lane & 3) == 0) {
                int r = warpM * 32 + tm * 16 + (lane >> 2) + half * 8;
                sPs[warpN * 128 + r] = ps;
                sPd[warpN * 128 + r] = pd;
            }
        }
    }
    __syncthreads();
    if (tid < 128) {
        int rg = rowBase + tid;
        if (rg < M) {
            als[(size_t)rg * H + head] = sPs[tid] + sPs[128 + tid];
            ald[(size_t)rg * H + head] = sPd[tid] + sPd[128 + tid];
        }
    }
}

// ---------------- layers 1&2: single-pass agg (shift-invariant softmax) ----------------
#define CHUNK 128
__global__ void gat_agg_ln(const __half2* __restrict__ hw, const float* __restrict__ als,
                           const float* __restrict__ ald, const float* __restrict__ bias,
                           const float* __restrict__ lng, const float* __restrict__ lnb,
                           __nv_bfloat16* __restrict__ fh, __nv_bfloat16* __restrict__ fl,
                           int nodeOff) {
    __shared__ int sidx[CHUNK];
    __shared__ float sS[4], sQ[4];

    int n = nodeOff + blockIdx.x;
    if (n >= NN) return;
    int tid = threadIdx.x;
    int h = tid >> 5;
    int lane = tid & 31;
    int grp = lane >> 3, gl = lane & 7;
    const __half* hwp = (const __half*)hw;

    int start = g_rowstart[n];
    int deg = g_count[n];
    float ald_n = ald[n * 4 + h];
    float e_self = lrelu(als[n * 4 + h] + ald_n);

    float acc[8];
#pragma unroll
    for (int k = 0; k < 8; k++) acc[k] = 0.0f;
    float s;

    if (deg <= CHUNK) {
        for (int j = tid; j < deg; j += 128) sidx[j] = g_csr[start + j];
        __syncthreads();

        float swl = 0.0f;
        for (int j0 = 0; j0 < deg; j0 += 8) {
#pragma unroll
            for (int u = 0; u < 2; u++) {
                int j = j0 + u * 4 + grp;
                if (j < deg) {
                    int sj = sidx[j];
                    float w = __expf(lrelu(__ldg(&als[sj * 4 + h]) + ald_n));
                    uint4 rv = *(const uint4*)(hwp + (size_t)(sj * 4 + h) * 64 + gl * 8);
                    const __half2* hp = (const __half2*)&rv;
#pragma unroll
                    for (int k = 0; k < 4; k++) {
                        float2 f = __half22float2(hp[k]);
                        acc[k * 2] += w * f.x;
                        acc[k * 2 + 1] += w * f.y;
                    }
                    swl += w;
                }
            }
        }
#pragma unroll
        for (int k = 0; k < 8; k++) {
            acc[k] += __shfl_xor_sync(0xffffffffu, acc[k], 8);
            acc[k] += __shfl_xor_sync(0xffffffffu, acc[k], 16);
        }
        swl += __shfl_xor_sync(0xffffffffu, swl, 8);
        swl += __shfl_xor_sync(0xffffffffu, swl, 16);
        float w = __expf(e_self);
        uint4 rv = *(const uint4*)(hwp + (size_t)(n * 4 + h) * 64 + gl * 8);
        const __half2* hp = (const __half2*)&rv;
#pragma unroll
        for (int k = 0; k < 4; k++) {
            float2 f = __half22float2(hp[k]);
            acc[k * 2] += w * f.x;
            acc[k * 2 + 1] += w * f.y;
        }
        s = swl + w;
    } else {
        float m = e_self, ss = 1.0f;
        uint4 rv = *(const uint4*)(hwp + (size_t)(n * 4 + h) * 64 + gl * 8);
        const __half2* hp = (const __half2*)&rv;
#pragma unroll
        for (int k = 0; k < 4; k++) {
            float2 f = __half22float2(hp[k]);
            acc[k * 2] = f.x; acc[k * 2 + 1] = f.y;
        }
        for (int j = 0; j < deg; j++) {
            int sj = __ldg(&g_csr[start + j]);
            float e = lrelu(__ldg(&als[sj * 4 + h]) + ald_n);
            uint4 rv2 = *(const uint4*)(hwp + (size_t)(sj * 4 + h) * 64 + gl * 8);
            const __half2* hp2 = (const __half2*)&rv2;
            if (e <= m) {
                float w = __expf(e - m);
                ss += w;
#pragma unroll
                for (int k = 0; k < 4; k++) {
                    float2 f = __half22float2(hp2[k]);
                    acc[k * 2] += w * f.x; acc[k * 2 + 1] += w * f.y;
                }
            } else {
                float r = __expf(m - e);
                ss = ss * r + 1.0f;
#pragma unroll
                for (int k = 0; k < 4; k++) {
                    float2 f = __half22float2(hp2[k]);
                    acc[k * 2] = acc[k * 2] * r + f.x;
                    acc[k * 2 + 1] = acc[k * 2 + 1] * r + f.y;
                }
                m = e;
            }
        }
        s = ss;
    }

    float inv = 1.0f / s;
    int colbase = h * 64 + gl * 8;
    float v[8];
#pragma unroll
    for (int k = 0; k < 8; k++)
        v[k] = acc[k] * inv + bias[colbase + k];

    float ls = 0.0f, lq = 0.0f;
#pragma unroll
    for (int k = 0; k < 8; k++) { ls += v[k]; lq += v[k] * v[k]; }
#pragma unroll
    for (int o = 16; o > 0; o >>= 1) {
        ls += __shfl_xor_sync(0xffffffffu, ls, o);
        lq += __shfl_xor_sync(0xffffffffu, lq, o);
    }
    ls *= 0.25f; lq *= 0.25f;
    if (lane == 0) { sS[h] = ls; sQ[h] = lq; }
    __syncthreads();
    float S = sS[0] + sS[1] + sS[2] + sS[3];
    float Q = sQ[0] + sQ[1] + sQ[2] + sQ[3];
    float mu = S * (1.0f / 256.0f);
    float var = Q * (1.0f / 256.0f) - mu * mu;
    float rs = rsqrtf(var + LN_EPS);

    if (grp == 0) {
        __nv_bfloat162 ph[4], pl[4];
#pragma unroll
        for (int k2 = 0; k2 < 4; k2++) {
            float o0 = (v[k2 * 2] - mu) * rs * lng[colbase + k2 * 2] + lnb[colbase + k2 * 2];
            float o1 = (v[k2 * 2 + 1] - mu) * rs * lng[colbase + k2 * 2 + 1] + lnb[colbase + k2 * 2 + 1];
            o0 = o0 > 0.0f ? o0 : 0.0f;
            o1 = o1 > 0.0f ? o1 : 0.0f;
            __nv_bfloat16 b0 = __float2bfloat16(o0), b1 = __float2bfloat16(o1);
            ph[k2] = __nv_bfloat162(b0, b1);
            pl[k2] = __nv_bfloat162(__float2bfloat16(o0 - __bfloat162float(b0)),
                                    __float2bfloat16(o1 - __bfloat162float(b1)));
        }
        *(uint4*)&fh[(size_t)n * 256 + colbase] = *(uint4*)ph;
        *(uint4*)&fl[(size_t)n * 256 + colbase] = *(uint4*)pl;
    }
}

// ---------------- layer 3: H=1, C=64, warp per node, single pass ----------------
#define CHUNKW 128
__global__ void gat_agg_out(const __half2* __restrict__ hw, const float* __restrict__ als,
                            const float* __restrict__ ald, const float* __restrict__ bias,
                            float* __restrict__ out) {
    __shared__ int sidx[8][CHUNKW];
    int warp = threadIdx.x >> 5;
    int lane = threadIdx.x & 31;
    int grp = lane >> 3, gl = lane & 7;
    int n = blockIdx.x * 8 + warp;
    if (n >= NN) return;
    const __half* hwp = (const __half*)hw;

    int start = g_rowstart[n];
    int deg = g_count[n];
    float ald_n = ald[n];
    float e_self = lrelu(als[n] + ald_n);

    float acc[8];
#pragma unroll
    for (int k = 0; k < 8; k++) acc[k] = 0.0f;
    float s;

    if (deg <= CHUNKW) {
        for (int j = lane; j < deg; j += 32) sidx[warp][j] = g_csr[start + j];
        __syncwarp();

        float swl = 0.0f;
        for (int j0 = 0; j0 < deg; j0 += 8) {
#pragma unroll
            for (int u = 0; u < 2; u++) {
                int j = j0 + u * 4 + grp;
                if (j < deg) {
                    int sj = sidx[warp][j];
                    float w = __expf(lrelu(__ldg(&als[sj]) + ald_n));
                    uint4 rv = *(const uint4*)(hwp + (size_t)sj * 64 + gl * 8);
                    const __half2* hp = (const __half2*)&rv;
#pragma unroll
                    for (int k = 0; k < 4; k++) {
                        float2 f = __half22float2(hp[k]);
                        acc[k * 2] += w * f.x;
                        acc[k * 2 + 1] += w * f.y;
                    }
                    swl += w;
                }
            }
        }
#pragma unroll
        for (int k = 0; k < 8; k++) {
            acc[k] += __shfl_xor_sync(0xffffffffu, acc[k], 8);
            acc[k] += __shfl_xor_sync(0xffffffffu, acc[k], 16);
        }
        swl += __shfl_xor_sync(0xffffffffu, swl, 8);
        swl += __shfl_xor_sync(0xffffffffu, swl, 16);
        float w = __expf(e_self);
        uint4 rv = *(const uint4*)(hwp + (size_t)n * 64 + gl * 8);
        const __half2* hp = (const __half2*)&rv;
#pragma unroll
        for (int k = 0; k < 4; k++) {
            float2 f = __half22float2(hp[k]);
            acc[k * 2] += w * f.x;
            acc[k * 2 + 1] += w * f.y;
        }
        s = swl + w;
    } else {
        float m = e_self, ss = 1.0f;
        uint4 rv = *(const uint4*)(hwp + (size_t)n * 64 + gl * 8);
        const __half2* hp = (const __half2*)&rv;
#pragma unroll
        for (int k = 0; k < 4; k++) {
            float2 f = __half22float2(hp[k]);
            acc[k * 2] = f.x; acc[k * 2 + 1] = f.y;
        }
        for (int j = 0; j < deg; j++) {
            int sj = __ldg(&g_csr[start + j]);
            float e = lrelu(__ldg(&als[sj]) + ald_n);
            uint4 rv2 = *(const uint4*)(hwp + (size_t)sj * 64 + gl * 8);
            const __half2* hp2 = (const __half2*)&rv2;
            if (e <= m) {
                float w = __expf(e - m);
                ss += w;
#pragma unroll
                for (int k = 0; k < 4; k++) {
                    float2 f = __half22float2(hp2[k]);
                    acc[k * 2] += w * f.x; acc[k * 2 + 1] += w * f.y;
                }
            } else {
                float r = __expf(m - e);
                ss = ss * r + 1.0f;
#pragma unroll
                for (int k = 0; k < 4; k++) {
                    float2 f = __half22float2(hp2[k]);
                    acc[k * 2] = acc[k * 2] * r + f.x;
                    acc[k * 2 + 1] = acc[k * 2 + 1] * r + f.y;
                }
                m = e;
            }
        }
        s = ss;
    }

    if (grp == 0) {
        float inv = 1.0f / s;
        int colbase = gl * 8;
        float4 o0, o1;
        o0.x = acc[0] * inv + bias[colbase + 0];
        o0.y = acc[1] * inv + bias[colbase + 1];
        o0.z = acc[2] * inv + bias[colbase + 2];
        o0.w = acc[3] * inv + bias[colbase + 3];
        o1.x = acc[4] * inv + bias[colbase + 4];
        o1.y = acc[5] * inv + bias[colbase + 5];
        o1.z = acc[6] * inv + bias[colbase + 6];
        o1.w = acc[7] * inv + bias[colbase + 7];
        *(float4*)&out[(size_t)n * 64 + colbase] = o0;
        *(float4*)&out[(size_t)n * 64 + colbase + 4] = o1;
    }
}

// ---------------- driver ----------------
extern "C" void kernel_launch(void* const* d_in, const int* in_sizes, int n_in,
                              void* d_out, int out_size) {
    const float* x   = (const float*)d_in[0];
    const void*  ei  = d_in[1];
    const float* W1  = (const float*)d_in[2];
    const float* a1s = (const float*)d_in[3];
    const float* a1d = (const float*)d_in[4];
    const float* b1  = (const float*)d_in[5];
    const float* l1g = (const float*)d_in[6];
    const float* l1b = (const float*)d_in[7];
    const float* W2  = (const float*)d_in[8];
    const float* a2s = (const float*)d_in[9];
    const float* a2d = (const float*)d_in[10];
    const float* b2  = (const float*)d_in[11];
    const float* l2g = (const float*)d_in[12];
    const float* l2b = (const float*)d_in[13];
    const float* W3  = (const float*)d_in[14];
    const float* a3s = (const float*)d_in[15];
    const float* a3d = (const float*)d_in[16];
    const float* b3  = (const float*)d_in[17];
    float* out = (float*)d_out;

    __half2* hw;  cudaGetSymbolAddress((void**)&hw, g_hw);
    __nv_bfloat16* ah;  cudaGetSymbolAddress((void**)&ah, g_ah);
    __nv_bfloat16* al;  cudaGetSymbolAddress((void**)&al, g_al);
    __nv_bfloat16 *wth1, *wtl1, *wth2, *wtl2, *wth3, *wtl3;
    cudaGetSymbolAddress((void**)&wth1, g_wth1);
    cudaGetSymbolAddress((void**)&wtl1, g_wtl1);
    cudaGetSymbolAddress((void**)&wth2, g_wth2);
    cudaGetSymbolAddress((void**)&wtl2, g_wtl2);
    cudaGetSymbolAddress((void**)&wth3, g_wth3);
    cudaGetSymbolAddress((void**)&wtl3, g_wtl3);
    float* als;   cudaGetSymbolAddress((void**)&als, g_als);
    float* ald;   cudaGetSymbolAddress((void**)&ald, g_ald);

    static cudaStream_t sB = nullptr, sC = nullptr, sD = nullptr;
    static cudaEvent_t evRoot = nullptr, evCsr = nullptr, evTw2 = nullptr, evTw3 = nullptr;
    static cudaEvent_t evA1a = nullptr, evG2a = nullptr, evA2a = nullptr, evG3a = nullptr;
    if (!sB) {
        cudaFuncSetAttribute(gemm_bf16p, cudaFuncAttributeMaxDynamicSharedMemorySize, GEMM_SMEM);
        cudaStreamCreateWithFlags(&sB, cudaStreamNonBlocking);
        cudaStreamCreateWithFlags(&sC, cudaStreamNonBlocking);
        cudaStreamCreateWithFlags(&sD, cudaStreamNonBlocking);
        cudaEventCreateWithFlags(&evRoot, cudaEventDisableTiming);
        cudaEventCreateWithFlags(&evCsr, cudaEventDisableTiming);
        cudaEventCreateWithFlags(&evTw2, cudaEventDisableTiming);
        cudaEventCreateWithFlags(&evTw3, cudaEventDisableTiming);
        cudaEventCreateWithFlags(&evA1a, cudaEventDisableTiming);
        cudaEventCreateWithFlags(&evG2a, cudaEventDisableTiming);
        cudaEventCreateWithFlags(&evA2a, cudaEventDisableTiming);
        cudaEventCreateWithFlags(&evG3a, cudaEventDisableTiming);
    }

    const int grAll = (NN + 127) / 128;          // 391
    const int grA = HALF1 / 128;                 // 196 (rows [0, HALF1))
    const int grB = (NN - HALF1 + 127) / 128;    // 195 (rows [HALF1, NN))
    const int nB = NN - HALF1;                   // 24912

    transposeW_split<<<(128 * 256 + 255) / 256, 256>>>(W1, wth1, wtl1, 128, 256);  // 0
    split_input<<<(NN * 64 + 255) / 256, 256>>>(x, ah, al, NN * 64);               // 1
    cudaEventRecord(evRoot, 0);
    cudaStreamWaitEvent(sB, evRoot, 0);
    cudaStreamWaitEvent(sC, evRoot, 0);
    detect_width<<<1, 1, 0, sB>>>(ei);                                             // 2
    gemm_bf16p<<<dim3(grAll, 4), 256, GEMM_SMEM>>>(ah, al, wth1, wtl1, hw,         // 3 (profiled)
                                                   a1s, a1d, als, ald, 0, NN, 128, 256, 4);
    zero_counts<<<(NN + 255) / 256, 256, 0, sB>>>();
    count_edges<<<(NE + 255) / 256, 256, 0, sB>>>(ei);
    scan_stage1<<<NPART, 256, 0, sB>>>();
    scan_stage2<<<1, 32, 0, sB>>>();
    scan_stage3<<<NPART, 256, 0, sB>>>();
    scatter_edges<<<(NE + 255) / 256, 256, 0, sB>>>(ei);
    cudaEventRecord(evCsr, sB);
    transposeW_split<<<(256 * 256 + 255) / 256, 256, 0, sC>>>(W2, wth2, wtl2, 256, 256);
    cudaEventRecord(evTw2, sC);
    transposeW_split<<<(256 * 64 + 255) / 256, 256, 0, sC>>>(W3, wth3, wtl3, 256, 64);
    cudaEventRecord(evTw3, sC);

    // ---- layer 1 agg, split into halves; gemm2a overlaps agg1b ----
    cudaStreamWaitEvent(0, evCsr, 0);
    gat_agg_ln<<<HALF1, 128>>>(hw, als, ald, b1, l1g, l1b, ah, al, 0);
    cudaEventRecord(evA1a, 0);
    gat_agg_ln<<<nB, 128>>>(hw, als, ald, b1, l1g, l1b, ah, al, HALF1);

    cudaStreamWaitEvent(sD, evA1a, 0);
    cudaStreamWaitEvent(sD, evTw2, 0);
    gemm_bf16p<<<dim3(grA, 4), 256, GEMM_SMEM, sD>>>(ah, al, wth2, wtl2, hw, a2s, a2d,
                                                     als, ald, 0, NN, 256, 256, 4);
    cudaEventRecord(evG2a, sD);

    cudaStreamWaitEvent(0, evTw2, 0);
    gemm_bf16p<<<dim3(grB, 4), 256, GEMM_SMEM>>>(ah, al, wth2, wtl2, hw, a2s, a2d,
                                                 als, ald, HALF1, NN, 256, 256, 4);
    cudaStreamWaitEvent(0, evG2a, 0);

    // ---- layer 2 agg, split; gemm3a overlaps agg2b ----
    gat_agg_ln<<<HALF1, 128>>>(hw, als, ald, b2, l2g, l2b, ah, al, 0);
    cudaEventRecord(evA2a, 0);
    gat_agg_ln<<<nB, 128>>>(hw, als, ald, b2, l2g, l2b, ah, al, HALF1);

    cudaStreamWaitEvent(sD, evA2a, 0);
    cudaStreamWaitEvent(sD, evTw3, 0);
    gemm_bf16p<<<dim3(grA, 1), 256, GEMM_SMEM, sD>>>(ah, al, wth3, wtl3, hw, a3s, a3d,
                                                     als, ald, 0, NN, 256, 64, 1);
    cudaEventRecord(evG3a, sD);

    cudaStreamWaitEvent(0, evTw3, 0);
    gemm_bf16p<<<dim3(grB, 1), 256, GEMM_SMEM>>>(ah, al, wth3, wtl3, hw, a3s, a3d,
                                                 als, ald, HALF1, NN, 256, 64, 1);
    cudaStreamWaitEvent(0, evG3a, 0);

    gat_agg_out<<<(NN + 7) / 8, 256>>>(hw, als, ald, b3, out);
}

// round 15
// speedup vs baseline: 1.0355x; 1.0355x over previous
#include <cuda_runtime.h>
#include <cuda_bf16.h>
#include <cuda_fp16.h>
#include <cstdint>

#define NN 50000
#define NE 800000
#define LN_EPS 1e-5f
#define NEG_SLOPE 0.2f
#define NPART 49

// ---------------- static scratch (no allocs allowed) ----------------
__device__ __half2 g_hw[(size_t)NN * 128];          // GEMM output h, fp16
__device__ __nv_bfloat16 g_ah[(size_t)NN * 256];    // feat hi (layers 2/3 A operand)
__device__ __nv_bfloat16 g_al[(size_t)NN * 256];    // feat lo
__device__ __nv_bfloat16 g_wth1[256 * 256];
__device__ __nv_bfloat16 g_wtl1[256 * 256];
__device__ __nv_bfloat16 g_wth2[256 * 256];
__device__ __nv_bfloat16 g_wtl2[256 * 256];
__device__ __nv_bfloat16 g_wth3[256 * 64];
__device__ __nv_bfloat16 g_wtl3[256 * 64];
__device__ float g_als[(size_t)NN * 4];
__device__ float g_ald[(size_t)NN * 4];
__device__ int   g_count[NN];
__device__ int   g_rowstart[NN];
__device__ int   g_cursor[NN];
__device__ int   g_csr[NE];
__device__ int   g_part[NPART];
__device__ int   g_partscan[NPART];
__device__ int   g_is64;

// ---------------- helpers ----------------
__device__ __forceinline__ uint32_t smem_u32(const void* p) {
    uint32_t a;
    asm("{ .reg .u64 t; cvta.to.shared.u64 t, %1; cvt.u32.u64 %0, t; }" : "=r"(a) : "l"(p));
    return a;
}
__device__ __forceinline__ void ldmx4(uint32_t* r, uint32_t addr) {
    asm volatile("ldmatrix.sync.aligned.m8n8.x4.shared.b16 {%0,%1,%2,%3}, [%4];"
                 : "=r"(r[0]), "=r"(r[1]), "=r"(r[2]), "=r"(r[3]) : "r"(addr));
}
__device__ __forceinline__ void mma16816(float* c, const uint32_t* a, uint32_t b0, uint32_t b1) {
    asm volatile("mma.sync.aligned.m16n8k16.row.col.f32.bf16.bf16.f32 "
                 "{%0,%1,%2,%3}, {%4,%5,%6,%7}, {%8,%9}, {%0,%1,%2,%3};"
                 : "+f"(c[0]), "+f"(c[1]), "+f"(c[2]), "+f"(c[3])
                 : "r"(a[0]), "r"(a[1]), "r"(a[2]), "r"(a[3]), "r"(b0), "r"(b1));
}
__device__ __forceinline__ void cpa16(uint32_t d, const void* s) {
    asm volatile("cp.async.ca.shared.global [%0], [%1], 16;" :: "r"(d), "l"(s));
}
#define CP_COMMIT() asm volatile("cp.async.commit_group;" ::: "memory")
#define CP_WAIT(n)  asm volatile("cp.async.wait_group %0;" :: "n"(n) : "memory")

__device__ __forceinline__ float lrelu(float v) { return v >= 0.0f ? v : NEG_SLOPE * v; }
__device__ __forceinline__ int load_idx(const void* ei, long long pos) {
    if (g_is64) return (int)((const long long*)ei)[pos];
    return ((const int*)ei)[pos];
}

// ---------------- edge-index width detection ----------------
__global__ void detect_width(const void* ei) {
    const int* p = (const int*)ei;
    int is64 = 1;
    for (int i = 0; i < 16; i++)
        if (p[2 * i + 1] != 0) { is64 = 0; break; }
    g_is64 = is64;
}

// ---------------- CSR build ----------------
__global__ void zero_counts() {
    int i = blockIdx.x * blockDim.x + threadIdx.x;
    if (i < NN) g_count[i] = 0;
}
__global__ void count_edges(const void* __restrict__ ei) {
    int i = blockIdx.x * blockDim.x + threadIdx.x;
    if (i >= NE) return;
    atomicAdd(&g_count[load_idx(ei, (long long)NE + i)], 1);
}
__global__ void scan_stage1() {
    int b = blockIdx.x, t = threadIdx.x;
    int base = b * 1024 + t * 4;
    int s = 0;
#pragma unroll
    for (int j = 0; j < 4; j++) { int idx = base + j; if (idx < NN) s += g_count[idx]; }
    __shared__ int sm[256];
    sm[t] = s;
    __syncthreads();
    for (int off = 128; off > 0; off >>= 1) { if (t < off) sm[t] += sm[t + off]; __syncthreads(); }
    if (t == 0) g_part[b] = sm[0];
}
__global__ void scan_stage2() {
    if (threadIdx.x == 0) {
        int run = 0;
        for (int i = 0; i < NPART; i++) { g_partscan[i] = run; run += g_part[i]; }
    }
}
__global__ void scan_stage3() {
    int b = blockIdx.x, t = threadIdx.x;
    int base = b * 1024 + t * 4;
    int v[4]; int tsum = 0;
#pragma unroll
    for (int j = 0; j < 4; j++) { int idx = base + j; v[j] = (idx < NN) ? g_count[idx] : 0; tsum += v[j]; }
    __shared__ int sm[256];
    sm[t] = tsum;
    __syncthreads();
    for (int off = 1; off < 256; off <<= 1) {
        int add = (t >= off) ? sm[t - off] : 0;
        __syncthreads(); sm[t] += add; __syncthreads();
    }
    int run = g_partscan[b] + sm[t] - tsum;
#pragma unroll
    for (int j = 0; j < 4; j++) {
        int idx = base + j;
        if (idx < NN) { g_rowstart[idx] = run; g_cursor[idx] = run; run += v[j]; }
    }
}
__global__ void scatter_edges(const void* __restrict__ ei) {
    int i = blockIdx.x * blockDim.x + threadIdx.x;
    if (i >= NE) return;
    int src = load_idx(ei, i);
    int dst = load_idx(ei, (long long)NE + i);
    g_csr[atomicAdd(&g_cursor[dst], 1)] = src;
}

// ---------------- weight transpose + split ----------------
__global__ void transposeW_split(const float* __restrict__ W, __nv_bfloat16* __restrict__ Wth,
                                 __nv_bfloat16* __restrict__ Wtl, int K, int Ncol) {
    int i = blockIdx.x * 256 + threadIdx.x;
    if (i < K * Ncol) {
        int k = i / Ncol, n = i % Ncol;
        float v = W[i];
        __nv_bfloat16 h = __float2bfloat16(v);
        Wth[n * K + k] = h;
        Wtl[n * K + k] = __float2bfloat16(v - __bfloat162float(h));
    }
}

struct BF4 { __nv_bfloat162 a, b; };

// ---------------- layer-1 GEMM: A fp32 (inline split), B pre-split ----------------
#define LDA 40
#define O1_AH 0
#define O1_AL 10240
#define O1_BH 20480
#define O1_BL 25600
#define O1_PS 30720
#define O1_PD 31744
#define G1_SMEM 32768

__global__ void __launch_bounds__(256) gemm1_f32a(const float* __restrict__ A,
                                                  const __nv_bfloat16* __restrict__ Bh,
                                                  const __nv_bfloat16* __restrict__ Bl,
                                                  __half2* __restrict__ C,
                                                  const float* __restrict__ a_s,
                                                  const float* __restrict__ a_d,
                                                  float* __restrict__ als,
                                                  float* __restrict__ ald,
                                                  int M, int K, int Ncol, int H) {
    extern __shared__ char smem[];
    uint32_t sb = smem_u32(smem);
    float* sPs = (float*)(smem + O1_PS);
    float* sPd = (float*)(smem + O1_PD);

    int tid = threadIdx.x;
    int lane = tid & 31, wid = tid >> 5;
    int warpM = wid & 3, warpN = wid >> 2;
    int rowBase = blockIdx.x * 128, colBase = blockIdx.y * 64;
    int head = blockIdx.y;

    float acc[2][4][4];
#pragma unroll
    for (int i = 0; i < 2; i++)
#pragma unroll
        for (int j = 0; j < 4; j++)
#pragma unroll
            for (int q = 0; q < 4; q++) acc[i][j][q] = 0.0f;

    int br = tid >> 2, bc = (tid & 3) * 8;
    int brg = colBase + br;

    int rowA = warpM * 32 + (lane & 15);
    int colA = (lane >> 4) * 8;
    int rowB = warpN * 32 + (lane & 7) + ((lane >> 4) << 3);
    int colB = ((lane >> 3) & 1) * 8;

    int nT = K >> 5;  // 4
    for (int t = 0; t < nT; t++) {
        int kt = t * 32;
        cpa16(sb + O1_BH + (br * LDA + bc) * 2, Bh + (size_t)brg * K + kt + bc);
        cpa16(sb + O1_BL + (br * LDA + bc) * 2, Bl + (size_t)brg * K + kt + bc);
        CP_COMMIT();
#pragma unroll
        for (int i = 0; i < 4; i++) {
            int p = tid + i * 256;
            int row = p >> 3, c4 = p & 7;
            int rg = rowBase + row; if (rg >= M) rg = M - 1;
            float4 v = *(const float4*)(A + (size_t)rg * K + kt + c4 * 4);
            __nv_bfloat16 hx = __float2bfloat16(v.x), hy = __float2bfloat16(v.y);
            __nv_bfloat16 hz = __float2bfloat16(v.z), hw = __float2bfloat16(v.w);
            BF4 hi, lo;
            hi.a = __nv_bfloat162(hx, hy);
            hi.b = __nv_bfloat162(hz, hw);
            lo.a = __nv_bfloat162(__float2bfloat16(v.x - __bfloat162float(hx)),
                                  __float2bfloat16(v.y - __bfloat162float(hy)));
            lo.b = __nv_bfloat162(__float2bfloat16(v.z - __bfloat162float(hz)),
                                  __float2bfloat16(v.w - __bfloat162float(hw)));
            *(BF4*)(smem + O1_AH + (row * LDA + c4 * 4) * 2) = hi;
            *(BF4*)(smem + O1_AL + (row * LDA + c4 * 4) * 2) = lo;
        }
        CP_WAIT(0);
        __syncthreads();

#pragma unroll
        for (int ks = 0; ks < 2; ks++) {
            int k0 = ks * 16;
            uint32_t ah[2][4], al[2][4];
#pragma unroll
            for (int tm = 0; tm < 2; tm++) {
                uint32_t off = (uint32_t)(((rowA + tm * 16) * LDA + k0 + colA) * 2);
                ldmx4(ah[tm], sb + O1_AH + off);
                ldmx4(al[tm], sb + O1_AL + off);
            }
            uint32_t bh[2][4], bl[2][4];
#pragma unroll
            for (int g = 0; g < 2; g++) {
                uint32_t off = (uint32_t)(((rowB + g * 16) * LDA + k0 + colB) * 2);
                ldmx4(bh[g], sb + O1_BH + off);
                ldmx4(bl[g], sb + O1_BL + off);
            }
#pragma unroll
            for (int tm = 0; tm < 2; tm++) {
#pragma unroll
                for (int tn = 0; tn < 4; tn++) {
                    int g = tn >> 1, q = (tn & 1) * 2;
                    mma16816(acc[tm][tn], ah[tm], bh[g][q], bh[g][q + 1]);
                    mma16816(acc[tm][tn], ah[tm], bl[g][q], bl[g][q + 1]);
                    mma16816(acc[tm][tn], al[tm], bh[g][q], bh[g][q + 1]);
                }
            }
        }
        __syncthreads();
    }

#pragma unroll
    for (int tm = 0; tm < 2; tm++) {
        int r0 = rowBase + warpM * 32 + tm * 16 + (lane >> 2);
#pragma unroll
        for (int tn = 0; tn < 4; tn++) {
            int c = colBase + warpN * 32 + tn * 8 + (lane & 3) * 2;
            if (r0 < M)
                C[((size_t)r0 * Ncol + c) >> 1] = __floats2half2_rn(acc[tm][tn][0], acc[tm][tn][1]);
            if (r0 + 8 < M)
                C[((size_t)(r0 + 8) * Ncol + c) >> 1] = __floats2half2_rn(acc[tm][tn][2], acc[tm][tn][3]);
        }
    }

    float asv[8], adv[8];
#pragma unroll
    for (int tn = 0; tn < 4; tn++) {
        int cl = warpN * 32 + tn * 8 + (lane & 3) * 2;
        asv[tn * 2] = a_s[head * 64 + cl];
        asv[tn * 2 + 1] = a_s[head * 64 + cl + 1];
        adv[tn * 2] = a_d[head * 64 + cl];
        adv[tn * 2 + 1] = a_d[head * 64 + cl + 1];
    }
#pragma unroll
    for (int tm = 0; tm < 2; tm++) {
#pragma unroll
        for (int half = 0; half < 2; half++) {
            float ps = 0.0f, pd = 0.0f;
#pragma unroll
            for (int tn = 0; tn < 4; tn++) {
                ps += acc[tm][tn][half * 2] * asv[tn * 2] + acc[tm][tn][half * 2 + 1] * asv[tn * 2 + 1];
                pd += acc[tm][tn][half * 2] * adv[tn * 2] + acc[tm][tn][half * 2 + 1] * adv[tn * 2 + 1];
            }
            ps += __shfl_xor_sync(0xffffffffu, ps, 1);
            ps += __shfl_xor_sync(0xffffffffu, ps, 2);
            pd += __shfl_xor_sync(0xffffffffu, pd, 1);
            pd += __shfl_xor_sync(0xffffffffu, pd, 2);
            if ((lane & 3) == 0) {
                int r = warpM * 32 + tm * 16 + (lane >> 2) + half * 8;
                sPs[warpN * 128 + r] = ps;
                sPd[warpN * 128 + r] = pd;
            }
        }
    }
    __syncthreads();
    if (tid < 128) {
        int rg = rowBase + tid;
        if (rg < M) {
            als[(size_t)rg * H + head] = sPs[tid] + sPs[128 + tid];
            ald[(size_t)rg * H + head] = sPd[tid] + sPd[128 + tid];
        }
    }
}

// ---------------- layers 2/3 GEMM (pre-split operands, cp.async double-buffer) ----------------
#define ABUF 10240
#define BBUF 5120
#define OFF_AH 0
#define OFF_AL 20480
#define OFF_BH 40960
#define OFF_BL 51200
#define OFF_PS 61440
#define OFF_PD 62464
#define GEMM_SMEM 63488

__global__ void __launch_bounds__(256) gemm_bf16p(const __nv_bfloat16* __restrict__ Ah,
                                                  const __nv_bfloat16* __restrict__ Al,
                                                  const __nv_bfloat16* __restrict__ Bh,
                                                  const __nv_bfloat16* __restrict__ Bl,
                                                  __half2* __restrict__ C,
                                                  const float* __restrict__ a_s,
                                                  const float* __restrict__ a_d,
                                                  float* __restrict__ als,
                                                  float* __restrict__ ald,
                                                  int M, int K, int Ncol, int H) {
    extern __shared__ char smem[];
    uint32_t sb = smem_u32(smem);
    float* sPs = (float*)(smem + OFF_PS);
    float* sPd = (float*)(smem + OFF_PD);

    int tid = threadIdx.x;
    int lane = tid & 31, wid = tid >> 5;
    int warpM = wid & 3, warpN = wid >> 2;
    int rowBase = blockIdx.x * 128, colBase = blockIdx.y * 64;
    int head = blockIdx.y;

    float acc[2][4][4];
#pragma unroll
    for (int i = 0; i < 2; i++)
#pragma unroll
        for (int j = 0; j < 4; j++)
#pragma unroll
            for (int q = 0; q < 4; q++) acc[i][j][q] = 0.0f;

    int ar0 = tid >> 2, ac0 = (tid & 3) * 8;
    int ar1 = (tid + 256) >> 2;
    int rg0 = rowBase + ar0; if (rg0 >= M) rg0 = M - 1;
    int rg1 = rowBase + ar1; if (rg1 >= M) rg1 = M - 1;
    int br = tid >> 2, bc = (tid & 3) * 8;
    int brg = colBase + br;

    auto load_tile = [&](int t, int b) {
        int kt = t * 32;
        uint32_t aH = sb + OFF_AH + b * ABUF;
        uint32_t aL = sb + OFF_AL + b * ABUF;
        uint32_t bH = sb + OFF_BH + b * BBUF;
        uint32_t bL = sb + OFF_BL + b * BBUF;
        cpa16(aH + (ar0 * LDA + ac0) * 2, Ah + (size_t)rg0 * K + kt + ac0);
        cpa16(aH + (ar1 * LDA + ac0) * 2, Ah + (size_t)rg1 * K + kt + ac0);
        cpa16(aL + (ar0 * LDA + ac0) * 2, Al + (size_t)rg0 * K + kt + ac0);
        cpa16(aL + (ar1 * LDA + ac0) * 2, Al + (size_t)rg1 * K + kt + ac0);
        cpa16(bH + (br * LDA + bc) * 2, Bh + (size_t)brg * K + kt + bc);
        cpa16(bL + (br * LDA + bc) * 2, Bl + (size_t)brg * K + kt + bc);
    };

    int rowA = warpM * 32 + (lane & 15);
    int colA = (lane >> 4) * 8;
    int rowB = warpN * 32 + (lane & 7) + ((lane >> 4) << 3);
    int colB = ((lane >> 3) & 1) * 8;

    int nT = K >> 5;
    load_tile(0, 0);
    CP_COMMIT();

    int buf = 0;
    for (int t = 0; t < nT; t++) {
        if (t + 1 < nT) {
            load_tile(t + 1, buf ^ 1);
            CP_COMMIT();
            CP_WAIT(1);
        } else {
            CP_WAIT(0);
        }
        __syncthreads();

        uint32_t aHiB = sb + OFF_AH + buf * ABUF;
        uint32_t aLoB = sb + OFF_AL + buf * ABUF;
        uint32_t bHiB = sb + OFF_BH + buf * BBUF;
        uint32_t bLoB = sb + OFF_BL + buf * BBUF;
#pragma unroll
        for (int ks = 0; ks < 2; ks++) {
            int k0 = ks * 16;
            uint32_t ah[2][4], al[2][4];
#pragma unroll
            for (int tm = 0; tm < 2; tm++) {
                uint32_t off = (uint32_t)(((rowA + tm * 16) * LDA + k0 + colA) * 2);
                ldmx4(ah[tm], aHiB + off);
                ldmx4(al[tm], aLoB + off);
            }
            uint32_t bh[2][4], bl[2][4];
#pragma unroll
            for (int g = 0; g < 2; g++) {
                uint32_t off = (uint32_t)(((rowB + g * 16) * LDA + k0 + colB) * 2);
                ldmx4(bh[g], bHiB + off);
                ldmx4(bl[g], bLoB + off);
            }
#pragma unroll
            for (int tm = 0; tm < 2; tm++) {
#pragma unroll
                for (int tn = 0; tn < 4; tn++) {
                    int g = tn >> 1, q = (tn & 1) * 2;
                    mma16816(acc[tm][tn], ah[tm], bh[g][q], bh[g][q + 1]);
                    mma16816(acc[tm][tn], ah[tm], bl[g][q], bl[g][q + 1]);
                    mma16816(acc[tm][tn], al[tm], bh[g][q], bh[g][q + 1]);
                }
            }
        }
        __syncthreads();
        buf ^= 1;
    }

#pragma unroll
    for (int tm = 0; tm < 2; tm++) {
        int r0 = rowBase + warpM * 32 + tm * 16 + (lane >> 2);
#pragma unroll
        for (int tn = 0; tn < 4; tn++) {
            int c = colBase + warpN * 32 + tn * 8 + (lane & 3) * 2;
            if (r0 < M)
                C[((size_t)r0 * Ncol + c) >> 1] = __floats2half2_rn(acc[tm][tn][0], acc[tm][tn][1]);
            if (r0 + 8 < M)
                C[((size_t)(r0 + 8) * Ncol + c) >> 1] = __floats2half2_rn(acc[tm][tn][2], acc[tm][tn][3]);
        }
    }

    float asv[8], adv[8];
#pragma unroll
    for (int tn = 0; tn < 4; tn++) {
        int cl = warpN * 32 + tn * 8 + (lane & 3) * 2;
        asv[tn * 2] = a_s[head * 64 + cl];
        asv[tn * 2 + 1] = a_s[head * 64 + cl + 1];
        adv[tn * 2] = a_d[head * 64 + cl];
        adv[tn * 2 + 1] = a_d[head * 64 + cl + 1];
    }
#pragma unroll
    for (int tm = 0; tm < 2; tm++) {
#pragma unroll
        for (int half = 0; half < 2; half++) {
            float ps = 0.0f, pd = 0.0f;
#pragma unroll
            for (int tn = 0; tn < 4; tn++) {
                ps += acc[tm][tn][half * 2] * asv[tn * 2] + acc[tm][tn][half * 2 + 1] * asv[tn * 2 + 1];
                pd += acc[tm][tn][half * 2] * adv[tn * 2] + acc[tm][tn][half * 2 + 1] * adv[tn * 2 + 1];
            }
            ps += __shfl_xor_sync(0xffffffffu, ps, 1);
            ps += __shfl_xor_sync(0xffffffffu, ps, 2);
            pd += __shfl_xor_sync(0xffffffffu, pd, 1);
            pd += __shfl_xor_sync(0xffffffffu, pd, 2);
            if ((lane & 3) == 0) {
                int r = warpM * 32 + tm * 16 + (lane >> 2) + half * 8;
                sPs[warpN * 128 + r] = ps;
                sPd[warpN * 128 + r] = pd;
            }
        }
    }
    __syncthreads();
    if (tid < 128) {
        int rg = rowBase + tid;
        if (rg < M) {
            als[(size_t)rg * H + head] = sPs[tid] + sPs[128 + tid];
            ald[(size_t)rg * H + head] = sPd[tid] + sPd[128 + tid];
        }
    }
}

// ---------------- layers 1&2: single-pass agg (shift-invariant softmax) ----------------
#define CHUNK 128
__global__ void gat_agg_ln(const __half2* __restrict__ hw, const float* __restrict__ als,
                           const float* __restrict__ ald, const float* __restrict__ bias,
                           const float* __restrict__ lng, const float* __restrict__ lnb,
                           __nv_bfloat16* __restrict__ fh, __nv_bfloat16* __restrict__ fl) {
    __shared__ int sidx[CHUNK];
    __shared__ float sS[4], sQ[4];

    int n = blockIdx.x;
    int tid = threadIdx.x;
    int h = tid >> 5;
    int lane = tid & 31;
    int grp = lane >> 3, gl = lane & 7;
    const __half* hwp = (const __half*)hw;

    int start = g_rowstart[n];
    int deg = g_count[n];
    float ald_n = ald[n * 4 + h];
    float e_self = lrelu(als[n * 4 + h] + ald_n);

    float acc[8];
#pragma unroll
    for (int k = 0; k < 8; k++) acc[k] = 0.0f;
    float s;

    if (deg <= CHUNK) {
        for (int j = tid; j < deg; j += 128) sidx[j] = g_csr[start + j];
        __syncthreads();

        float swl = 0.0f;
        for (int j0 = 0; j0 < deg; j0 += 8) {
#pragma unroll
            for (int u = 0; u < 2; u++) {
                int j = j0 + u * 4 + grp;
                if (j < deg) {
                    int sj = sidx[j];
                    float w = __expf(lrelu(__ldg(&als[sj * 4 + h]) + ald_n));
                    uint4 rv = *(const uint4*)(hwp + (size_t)(sj * 4 + h) * 64 + gl * 8);
                    const __half2* hp = (const __half2*)&rv;
#pragma unroll
                    for (int k = 0; k < 4; k++) {
                        float2 f = __half22float2(hp[k]);
                        acc[k * 2] += w * f.x;
                        acc[k * 2 + 1] += w * f.y;
                    }
                    swl += w;
                }
            }
        }
#pragma unroll
        for (int k = 0; k < 8; k++) {
            acc[k] += __shfl_xor_sync(0xffffffffu, acc[k], 8);
            acc[k] += __shfl_xor_sync(0xffffffffu, acc[k], 16);
        }
        swl += __shfl_xor_sync(0xffffffffu, swl, 8);
        swl += __shfl_xor_sync(0xffffffffu, swl, 16);
        float w = __expf(e_self);
        uint4 rv = *(const uint4*)(hwp + (size_t)(n * 4 + h) * 64 + gl * 8);
        const __half2* hp = (const __half2*)&rv;
#pragma unroll
        for (int k = 0; k < 4; k++) {
            float2 f = __half22float2(hp[k]);
            acc[k * 2] += w * f.x;
            acc[k * 2 + 1] += w * f.y;
        }
        s = swl + w;
    } else {
        float m = e_self, ss = 1.0f;
        uint4 rv = *(const uint4*)(hwp + (size_t)(n * 4 + h) * 64 + gl * 8);
        const __half2* hp = (const __half2*)&rv;
#pragma unroll
        for (int k = 0; k < 4; k++) {
            float2 f = __half22float2(hp[k]);
            acc[k * 2] = f.x; acc[k * 2 + 1] = f.y;
        }
        for (int j = 0; j < deg; j++) {
            int sj = __ldg(&g_csr[start + j]);
            float e = lrelu(__ldg(&als[sj * 4 + h]) + ald_n);
            uint4 rv2 = *(const uint4*)(hwp + (size_t)(sj * 4 + h) * 64 + gl * 8);
            const __half2* hp2 = (const __half2*)&rv2;
            if (e <= m) {
                float w = __expf(e - m);
                ss += w;
#pragma unroll
                for (int k = 0; k < 4; k++) {
                    float2 f = __half22float2(hp2[k]);
                    acc[k * 2] += w * f.x; acc[k * 2 + 1] += w * f.y;
                }
            } else {
                float r = __expf(m - e);
                ss = ss * r + 1.0f;
#pragma unroll
                for (int k = 0; k < 4; k++) {
                    float2 f = __half22float2(hp2[k]);
                    acc[k * 2] = acc[k * 2] * r + f.x;
                    acc[k * 2 + 1] = acc[k * 2 + 1] * r + f.y;
                }
                m = e;
            }
        }
        s = ss;
    }

    float inv = 1.0f / s;
    int colbase = h * 64 + gl * 8;
    float v[8];
#pragma unroll
    for (int k = 0; k < 8; k++)
        v[k] = acc[k] * inv + bias[colbase + k];

    float ls = 0.0f, lq = 0.0f;
#pragma unroll
    for (int k = 0; k < 8; k++) { ls += v[k]; lq += v[k] * v[k]; }
#pragma unroll
    for (int o = 16; o > 0; o >>= 1) {
        ls += __shfl_xor_sync(0xffffffffu, ls, o);
        lq += __shfl_xor_sync(0xffffffffu, lq, o);
    }
    ls *= 0.25f; lq *= 0.25f;
    if (lane == 0) { sS[h] = ls; sQ[h] = lq; }
    __syncthreads();
    float S = sS[0] + sS[1] + sS[2] + sS[3];
    float Q = sQ[0] + sQ[1] + sQ[2] + sQ[3];
    float mu = S * (1.0f / 256.0f);
    float var = Q * (1.0f / 256.0f) - mu * mu;
    float rs = rsqrtf(var + LN_EPS);

    if (grp == 0) {
        __nv_bfloat162 ph[4], pl[4];
#pragma unroll
        for (int k2 = 0; k2 < 4; k2++) {
            float o0 = (v[k2 * 2] - mu) * rs * lng[colbase + k2 * 2] + lnb[colbase + k2 * 2];
            float o1 = (v[k2 * 2 + 1] - mu) * rs * lng[colbase + k2 * 2 + 1] + lnb[colbase + k2 * 2 + 1];
            o0 = o0 > 0.0f ? o0 : 0.0f;
            o1 = o1 > 0.0f ? o1 : 0.0f;
            __nv_bfloat16 b0 = __float2bfloat16(o0), b1 = __float2bfloat16(o1);
            ph[k2] = __nv_bfloat162(b0, b1);
            pl[k2] = __nv_bfloat162(__float2bfloat16(o0 - __bfloat162float(b0)),
                                    __float2bfloat16(o1 - __bfloat162float(b1)));
        }
        *(uint4*)&fh[(size_t)n * 256 + colbase] = *(uint4*)ph;
        *(uint4*)&fl[(size_t)n * 256 + colbase] = *(uint4*)pl;
    }
}

// ---------------- layer 3: H=1, C=64, warp per node, single pass ----------------
#define CHUNKW 128
__global__ void gat_agg_out(const __half2* __restrict__ hw, const float* __restrict__ als,
                            const float* __restrict__ ald, const float* __restrict__ bias,
                            float* __restrict__ out) {
    __shared__ int sidx[8][CHUNKW];
    int warp = threadIdx.x >> 5;
    int lane = threadIdx.x & 31;
    int grp = lane >> 3, gl = lane & 7;
    int n = blockIdx.x * 8 + warp;
    if (n >= NN) return;
    const __half* hwp = (const __half*)hw;

    int start = g_rowstart[n];
    int deg = g_count[n];
    float ald_n = ald[n];
    float e_self = lrelu(als[n] + ald_n);

    float acc[8];
#pragma unroll
    for (int k = 0; k < 8; k++) acc[k] = 0.0f;
    float s;

    if (deg <= CHUNKW) {
        for (int j = lane; j < deg; j += 32) sidx[warp][j] = g_csr[start + j];
        __syncwarp();

        float swl = 0.0f;
        for (int j0 = 0; j0 < deg; j0 += 8) {
#pragma unroll
            for (int u = 0; u < 2; u++) {
                int j = j0 + u * 4 + grp;
                if (j < deg) {
                    int sj = sidx[warp][j];
                    float w = __expf(lrelu(__ldg(&als[sj]) + ald_n));
                    uint4 rv = *(const uint4*)(hwp + (size_t)sj * 64 + gl * 8);
                    const __half2* hp = (const __half2*)&rv;
#pragma unroll
                    for (int k = 0; k < 4; k++) {
                        float2 f = __half22float2(hp[k]);
                        acc[k * 2] += w * f.x;
                        acc[k * 2 + 1] += w * f.y;
                    }
                    swl += w;
                }
            }
        }
#pragma unroll
        for (int k = 0; k < 8; k++) {
            acc[k] += __shfl_xor_sync(0xffffffffu, acc[k], 8);
            acc[k] += __shfl_xor_sync(0xffffffffu, acc[k], 16);
        }
        swl += __shfl_xor_sync(0xffffffffu, swl, 8);
        swl += __shfl_xor_sync(0xffffffffu, swl, 16);
        float w = __expf(e_self);
        uint4 rv = *(const uint4*)(hwp + (size_t)n * 64 + gl * 8);
        const __half2* hp = (const __half2*)&rv;
#pragma unroll
        for (int k = 0; k < 4; k++) {
            float2 f = __half22float2(hp[k]);
            acc[k * 2] += w * f.x;
            acc[k * 2 + 1] += w * f.y;
        }
        s = swl + w;
    } else {
        float m = e_self, ss = 1.0f;
        uint4 rv = *(const uint4*)(hwp + (size_t)n * 64 + gl * 8);
        const __half2* hp = (const __half2*)&rv;
#pragma unroll
        for (int k = 0; k < 4; k++) {
            float2 f = __half22float2(hp[k]);
            acc[k * 2] = f.x; acc[k * 2 + 1] = f.y;
        }
        for (int j = 0; j < deg; j++) {
            int sj = __ldg(&g_csr[start + j]);
            float e = lrelu(__ldg(&als[sj]) + ald_n);
            uint4 rv2 = *(const uint4*)(hwp + (size_t)sj * 64 + gl * 8);
            const __half2* hp2 = (const __half2*)&rv2;
            if (e <= m) {
                float w = __expf(e - m);
                ss += w;
#pragma unroll
                for (int k = 0; k < 4; k++) {
                    float2 f = __half22float2(hp2[k]);
                    acc[k * 2] += w * f.x; acc[k * 2 + 1] += w * f.y;
                }
            } else {
                float r = __expf(m - e);
                ss = ss * r + 1.0f;
#pragma unroll
                for (int k = 0; k < 4; k++) {
                    float2 f = __half22float2(hp2[k]);
                    acc[k * 2] = acc[k * 2] * r + f.x;
                    acc[k * 2 + 1] = acc[k * 2 + 1] * r + f.y;
                }
                m = e;
            }
        }
        s = ss;
    }

    if (grp == 0) {
        float inv = 1.0f / s;
        int colbase = gl * 8;
        float4 o0, o1;
        o0.x = acc[0] * inv + bias[colbase + 0];
        o0.y = acc[1] * inv + bias[colbase + 1];
        o0.z = acc[2] * inv + bias[colbase + 2];
        o0.w = acc[3] * inv + bias[colbase + 3];
        o1.x = acc[4] * inv + bias[colbase + 4];
        o1.y = acc[5] * inv + bias[colbase + 5];
        o1.z = acc[6] * inv + bias[colbase + 6];
        o1.w = acc[7] * inv + bias[colbase + 7];
        *(float4*)&out[(size_t)n * 64 + colbase] = o0;
        *(float4*)&out[(size_t)n * 64 + colbase + 4] = o1;
    }
}

// ---------------- driver ----------------
extern "C" void kernel_launch(void* const* d_in, const int* in_sizes, int n_in,
                              void* d_out, int out_size) {
    const float* x   = (const float*)d_in[0];
    const void*  ei  = d_in[1];
    const float* W1  = (const float*)d_in[2];
    const float* a1s = (const float*)d_in[3];
    const float* a1d = (const float*)d_in[4];
    const float* b1  = (const float*)d_in[5];
    const float* l1g = (const float*)d_in[6];
    const float* l1b = (const float*)d_in[7];
    const float* W2  = (const float*)d_in[8];
    const float* a2s = (const float*)d_in[9];
    const float* a2d = (const float*)d_in[10];
    const float* b2  = (const float*)d_in[11];
    const float* l2g = (const float*)d_in[12];
    const float* l2b = (const float*)d_in[13];
    const float* W3  = (const float*)d_in[14];
    const float* a3s = (const float*)d_in[15];
    const float* a3d = (const float*)d_in[16];
    const float* b3  = (const float*)d_in[17];
    float* out = (float*)d_out;

    __half2* hw;  cudaGetSymbolAddress((void**)&hw, g_hw);
    __nv_bfloat16* ah;  cudaGetSymbolAddress((void**)&ah, g_ah);
    __nv_bfloat16* al;  cudaGetSymbolAddress((void**)&al, g_al);
    __nv_bfloat16 *wth1, *wtl1, *wth2, *wtl2, *wth3, *wtl3;
    cudaGetSymbolAddress((void**)&wth1, g_wth1);
    cudaGetSymbolAddress((void**)&wtl1, g_wtl1);
    cudaGetSymbolAddress((void**)&wth2, g_wth2);
    cudaGetSymbolAddress((void**)&wtl2, g_wtl2);
    cudaGetSymbolAddress((void**)&wth3, g_wth3);
    cudaGetSymbolAddress((void**)&wtl3, g_wtl3);
    float* als;   cudaGetSymbolAddress((void**)&als, g_als);
    float* ald;   cudaGetSymbolAddress((void**)&ald, g_ald);

    static cudaStream_t sB = nullptr, sC = nullptr;
    static cudaEvent_t evRoot = nullptr, evTw1 = nullptr, evCsr = nullptr,
                       evTw2 = nullptr, evTw3 = nullptr;
    if (!sB) {
        cudaFuncSetAttribute(gemm_bf16p, cudaFuncAttributeMaxDynamicSharedMemorySize, GEMM_SMEM);
        cudaFuncSetAttribute(gemm1_f32a, cudaFuncAttributeMaxDynamicSharedMemorySize, G1_SMEM);
        cudaStreamCreateWithFlags(&sB, cudaStreamNonBlocking);
        cudaStreamCreateWithFlags(&sC, cudaStreamNonBlocking);
        cudaEventCreateWithFlags(&evRoot, cudaEventDisableTiming);
        cudaEventCreateWithFlags(&evTw1, cudaEventDisableTiming);
        cudaEventCreateWithFlags(&evCsr, cudaEventDisableTiming);
        cudaEventCreateWithFlags(&evTw2, cudaEventDisableTiming);
        cudaEventCreateWithFlags(&evTw3, cudaEventDisableTiming);
    }

    int gr = (NN + 127) / 128;  // 391

    // fork side streams from the capturing stream FIRST (required for graph capture)
    cudaEventRecord(evRoot, 0);
    cudaStreamWaitEvent(sB, evRoot, 0);
    cudaStreamWaitEvent(sC, evRoot, 0);

    transposeW_split<<<(128 * 256 + 255) / 256, 256, 0, sC>>>(W1, wth1, wtl1, 128, 256);  // 0
    cudaEventRecord(evTw1, sC);
    detect_width<<<1, 1, 0, sB>>>(ei);                                             // 1
    zero_counts<<<(NN + 255) / 256, 256, 0, sB>>>();                               // 2
    cudaStreamWaitEvent(0, evTw1, 0);
    gemm1_f32a<<<dim3(gr, 4), 256, G1_SMEM>>>(x, wth1, wtl1, hw,                   // 3 (profiled)
                                              a1s, a1d, als, ald, NN, 128, 256, 4);
    count_edges<<<(NE + 255) / 256, 256, 0, sB>>>(ei);
    scan_stage1<<<NPART, 256, 0, sB>>>();
    scan_stage2<<<1, 32, 0, sB>>>();
    scan_stage3<<<NPART, 256, 0, sB>>>();
    scatter_edges<<<(NE + 255) / 256, 256, 0, sB>>>(ei);
    cudaEventRecord(evCsr, sB);
    transposeW_split<<<(256 * 256 + 255) / 256, 256, 0, sC>>>(W2, wth2, wtl2, 256, 256);
    cudaEventRecord(evTw2, sC);
    transposeW_split<<<(256 * 64 + 255) / 256, 256, 0, sC>>>(W3, wth3, wtl3, 256, 64);
    cudaEventRecord(evTw3, sC);

    cudaStreamWaitEvent(0, evCsr, 0);
    gat_agg_ln<<<NN, 128>>>(hw, als, ald, b1, l1g, l1b, ah, al);

    // Layer 2
    cudaStreamWaitEvent(0, evTw2, 0);
    gemm_bf16p<<<dim3(gr, 4), 256, GEMM_SMEM>>>(ah, al, wth2, wtl2, hw, a2s, a2d, als, ald,
                                                NN, 256, 256, 4);
    gat_agg_ln<<<NN, 128>>>(hw, als, ald, b2, l2g, l2b, ah, al);

    // Layer 3
    cudaStreamWaitEvent(0, evTw3, 0);
    gemm_bf16p<<<dim3(gr, 1), 256, GEMM_SMEM>>>(ah, al, wth3, wtl3, hw, a3s, a3d, als, ald,
                                                NN, 256, 64, 1);
    gat_agg_out<<<(NN + 7) / 8, 256>>>(hw, als, ald, b3, out);
}